// round 2
// baseline (speedup 1.0000x reference)
#include <cuda_runtime.h>
#include <cstdint>
#include <cstddef>

// Problem constants
#define BB   32
#define TT   4096
#define DD   512
#define GG   8
#define OUTD 512

#define NCHUNK 8
#define CHUNK  512          // TT / NCHUNK
#define OTILE  32           // output columns per K3 block

// -------- device scratch (no allocations allowed) --------
__device__ int   g_idx[TT];                       // token indices sorted by type (stable)
__device__ int   g_segstart[GG + 1];              // segment boundaries per group
__device__ float g_part[(size_t)BB * GG * NCHUNK * DD];   // partial sums [b][g][c][d]  (4 MB)
__device__ float g_pcnt[BB * GG * NCHUNK];                // partial counts [b][g][c]
__device__ float g_means[(size_t)GG * BB * DD];           // means [g][b][d] (0.5 MB)

// =====================================================================
// K1: deterministic stable counting sort of token_types (1 block, 512 thr)
// =====================================================================
__global__ void __launch_bounds__(512) k_sort(const int* __restrict__ types) {
    __shared__ int s[GG][512];
    __shared__ int base_s[GG + 1];
    const int tid = threadIdx.x;

    int ty[8];
    int lc[GG];
#pragma unroll
    for (int g = 0; g < GG; g++) lc[g] = 0;
#pragma unroll
    for (int k = 0; k < 8; k++) {
        const int t  = tid * 8 + k;
        const int tt = types[t];
        ty[k] = tt;
#pragma unroll
        for (int g = 0; g < GG; g++) lc[g] += (tt == g);
    }
#pragma unroll
    for (int g = 0; g < GG; g++) s[g][tid] = lc[g];
    __syncthreads();

    // Hillis-Steele inclusive scan over 512 entries, per group
    for (int off = 1; off < 512; off <<= 1) {
        int add[GG];
#pragma unroll
        for (int g = 0; g < GG; g++) add[g] = (tid >= off) ? s[g][tid - off] : 0;
        __syncthreads();
#pragma unroll
        for (int g = 0; g < GG; g++) s[g][tid] += add[g];
        __syncthreads();
    }

    if (tid == 0) {
        int b0 = 0;
        for (int g = 0; g < GG; g++) {
            base_s[g] = b0;
            g_segstart[g] = b0;
            b0 += s[g][511];
        }
        base_s[GG] = b0;
        g_segstart[GG] = b0;
    }
    __syncthreads();

    int cur[GG];
#pragma unroll
    for (int g = 0; g < GG; g++) cur[g] = base_s[g] + s[g][tid] - lc[g];
#pragma unroll
    for (int k = 0; k < 8; k++) {
        const int t  = tid * 8 + k;
        const int tt = ty[k];
#pragma unroll
        for (int g = 0; g < GG; g++) {
            if (tt == g) { g_idx[cur[g]] = t; cur[g]++; }
        }
    }
}

// =====================================================================
// K2: segmented partial sums. Grid (B, NCHUNK), 128 threads.
// Each thread owns 4 consecutive d (float4). One FFMA per loaded float.
// =====================================================================
__global__ void __launch_bounds__(128) k_partial(const float* __restrict__ batch,
                                                 const int* __restrict__ mask) {
    __shared__ int   t_s[CHUNK];
    __shared__ float f_s[CHUNK];
    __shared__ int   seg_s[GG + 1];

    const int tid = threadIdx.x;
    const int b   = blockIdx.x;
    const int c   = blockIdx.y;
    const int c0  = c * CHUNK;

    if (tid < GG + 1) seg_s[tid] = g_segstart[tid];
    for (int j = tid; j < CHUNK; j += 128) {
        const int t = g_idx[c0 + j];
        t_s[j] = t;
        f_s[j] = mask[b * TT + t] ? 0.0f : 1.0f;   // int32 bool: nonzero = padded
    }
    __syncthreads();

    float4 acc[GG];
    float  cnt[GG];
#pragma unroll
    for (int g = 0; g < GG; g++) {
        acc[g] = make_float4(0.f, 0.f, 0.f, 0.f);
        cnt[g] = 0.f;
    }

    const float* bb = batch + (size_t)b * TT * DD + tid * 4;

#pragma unroll
    for (int g = 0; g < GG; g++) {
        const int lo = max(seg_s[g], c0);
        const int hi = min(seg_s[g + 1], c0 + CHUNK);
#pragma unroll 4
        for (int j = lo; j < hi; j++) {
            const int   t = t_s[j - c0];
            const float f = f_s[j - c0];
            const float4 v = *(const float4*)(bb + (size_t)t * DD);
            acc[g].x = fmaf(v.x, f, acc[g].x);
            acc[g].y = fmaf(v.y, f, acc[g].y);
            acc[g].z = fmaf(v.z, f, acc[g].z);
            acc[g].w = fmaf(v.w, f, acc[g].w);
            cnt[g] += f;
        }
    }

#pragma unroll
    for (int g = 0; g < GG; g++) {
        *(float4*)&g_part[(((size_t)b * GG + g) * NCHUNK + c) * DD + tid * 4] = acc[g];
        if (tid == 0) g_pcnt[(b * GG + g) * NCHUNK + c] = cnt[g];
    }
}

// =====================================================================
// K2.5: reduce partials -> means [g][b][d]. Grid (B, G), 128 threads.
// =====================================================================
__global__ void __launch_bounds__(128) k_means() {
    const int b = blockIdx.x, g = blockIdx.y, tid = threadIdx.x;

    float4 s = make_float4(0.f, 0.f, 0.f, 0.f);
    float  cnt = 0.f;
#pragma unroll
    for (int c = 0; c < NCHUNK; c++) {
        const float4 p = *(const float4*)&g_part[(((size_t)b * GG + g) * NCHUNK + c) * DD + tid * 4];
        s.x += p.x; s.y += p.y; s.z += p.z; s.w += p.w;
        cnt += g_pcnt[(b * GG + g) * NCHUNK + c];
    }
    const float inv = (cnt > 0.f) ? (1.0f / cnt) : 0.0f;
    s.x *= inv; s.y *= inv; s.z *= inv; s.w *= inv;
    *(float4*)&g_means[((size_t)g * BB + b) * DD + tid * 4] = s;
}

// =====================================================================
// K3: per-group GEMM + bias. Grid (G, OUTD/OTILE), 128 threads.
// Thread owns 2 b-rows x 4 o-cols. W read exactly once chip-wide.
// means staged in smem in two d-halves (stays under 48 KB static).
// =====================================================================
#define HALF_D 256
#define MPITCH 260   // 260*4 bytes, 16B aligned, bank-conflict-free strides

__global__ void __launch_bounds__(128) k_gemm(const float* __restrict__ Wt,
                                              const float* __restrict__ bias,
                                              float* __restrict__ out) {
    __shared__ float mean_s[BB * MPITCH];   // [32][260] for the current d-half

    const int tid   = threadIdx.x;
    const int g     = blockIdx.x;
    const int obase = blockIdx.y * OTILE;

    const int olane = (tid & 7) * 4;        // 8 lanes x float4 = 32 cols
    const int b0    = (tid >> 3) * 2;       // 16 groups x 2 rows = 32 rows

    const float* msrc = &g_means[(size_t)g * BB * DD];
    const float* wp   = Wt + (size_t)g * DD * OUTD + obase + olane;

    float4 a0 = make_float4(0.f, 0.f, 0.f, 0.f);
    float4 a1 = make_float4(0.f, 0.f, 0.f, 0.f);

#pragma unroll
    for (int half = 0; half < 2; half++) {
        __syncthreads();
        // stage means[b][half*256 .. +256) into smem
        for (int i = tid; i < BB * (HALF_D / 4); i += 128) {
            const int bb2 = i / (HALF_D / 4);
            const int du  = i % (HALF_D / 4);
            const float4 v = *(const float4*)(msrc + (size_t)bb2 * DD + half * HALF_D + du * 4);
            *(float4*)&mean_s[bb2 * MPITCH + du * 4] = v;
        }
        __syncthreads();

        const float* m0 = &mean_s[b0 * MPITCH];
        const float* m1 = m0 + MPITCH;
        const float* wph = wp + (size_t)half * HALF_D * OUTD;
#pragma unroll 4
        for (int d = 0; d < HALF_D; d++) {
            const float4 w4 = *(const float4*)(wph + (size_t)d * OUTD);
            const float x0 = m0[d];
            const float x1 = m1[d];
            a0.x = fmaf(x0, w4.x, a0.x); a0.y = fmaf(x0, w4.y, a0.y);
            a0.z = fmaf(x0, w4.z, a0.z); a0.w = fmaf(x0, w4.w, a0.w);
            a1.x = fmaf(x1, w4.x, a1.x); a1.y = fmaf(x1, w4.y, a1.y);
            a1.z = fmaf(x1, w4.z, a1.z); a1.w = fmaf(x1, w4.w, a1.w);
        }
    }

    const int o = obase + olane;
    const float4 bv = *(const float4*)(bias + g * OUTD + o);
    a0.x += bv.x; a0.y += bv.y; a0.z += bv.z; a0.w += bv.w;
    a1.x += bv.x; a1.y += bv.y; a1.z += bv.z; a1.w += bv.w;

    *(float4*)(out + ((size_t)b0 * GG + g) * OUTD + o)       = a0;
    *(float4*)(out + ((size_t)(b0 + 1) * GG + g) * OUTD + o) = a1;
}

// =====================================================================
// Launch
// =====================================================================
extern "C" void kernel_launch(void* const* d_in, const int* in_sizes, int n_in,
                              void* d_out, int out_size) {
    const float* batch = (const float*)d_in[0];
    const float* Wt    = (const float*)d_in[1];
    const float* bias  = (const float*)d_in[2];
    const int*   types = (const int*)d_in[3];
    const int*   mask  = (const int*)d_in[4];   // bool upcast to int32: nonzero = padded
    float*       out   = (float*)d_out;

    (void)in_sizes; (void)n_in; (void)out_size;

    k_sort<<<1, 512>>>(types);
    k_partial<<<dim3(BB, NCHUNK), 128>>>(batch, mask);
    k_means<<<dim3(BB, GG), 128>>>();
    k_gemm<<<dim3(GG, OUTD / OTILE), 128>>>(Wt, bias, out);
}

// round 3
// speedup vs baseline: 4.0260x; 4.0260x over previous
#include <cuda_runtime.h>
#include <cstdint>
#include <cstddef>

// Problem constants
#define BB   32
#define TT   4096
#define DD   512
#define GG   8
#define OUTD 512

#define NCHUNK 32
#define CHUNK  128          // TT / NCHUNK == blockDim of k_partial

// K3 tiling
#define K3_OTILE 16
#define K3_QD    128        // d-quarter
#define MPITCH   132        // floats; banks (4b+d)%32 distinct for b in 0..7 per warp

// -------- device scratch (no allocations allowed) --------
__device__ int   g_idx[TT];                               // token indices sorted by type
__device__ int   g_segstart[GG + 1];                      // group segment boundaries
__device__ float g_part[(size_t)BB * GG * NCHUNK * DD];   // partial sums [b][g][c][d] (16 MB)
__device__ float g_pcnt[BB * GG * NCHUNK];                // partial counts [b][g][c]
__device__ float g_means[(size_t)GG * BB * DD];           // means [g][b][d] (0.5 MB)

// =====================================================================
// K1: deterministic stable counting sort of token_types (1 block, 512 thr)
// =====================================================================
__global__ void __launch_bounds__(512) k_sort(const int* __restrict__ types) {
    __shared__ int s[GG][512];
    __shared__ int base_s[GG + 1];
    const int tid = threadIdx.x;

    int ty[8];
    int lc[GG];
#pragma unroll
    for (int g = 0; g < GG; g++) lc[g] = 0;
#pragma unroll
    for (int k = 0; k < 8; k++) {
        const int t  = tid * 8 + k;
        const int tt = types[t];
        ty[k] = tt;
#pragma unroll
        for (int g = 0; g < GG; g++) lc[g] += (tt == g);
    }
#pragma unroll
    for (int g = 0; g < GG; g++) s[g][tid] = lc[g];
    __syncthreads();

    for (int off = 1; off < 512; off <<= 1) {
        int add[GG];
#pragma unroll
        for (int g = 0; g < GG; g++) add[g] = (tid >= off) ? s[g][tid - off] : 0;
        __syncthreads();
#pragma unroll
        for (int g = 0; g < GG; g++) s[g][tid] += add[g];
        __syncthreads();
    }

    if (tid == 0) {
        int b0 = 0;
        for (int g = 0; g < GG; g++) {
            base_s[g] = b0;
            g_segstart[g] = b0;
            b0 += s[g][511];
        }
        base_s[GG] = b0;
        g_segstart[GG] = b0;
    }
    __syncthreads();

    int cur[GG];
#pragma unroll
    for (int g = 0; g < GG; g++) cur[g] = base_s[g] + s[g][tid] - lc[g];
#pragma unroll
    for (int k = 0; k < 8; k++) {
        const int t  = tid * 8 + k;
        const int tt = ty[k];
#pragma unroll
        for (int g = 0; g < GG; g++) {
            if (tt == g) { g_idx[cur[g]] = t; cur[g]++; }
        }
    }
}

// =====================================================================
// K2: segmented partial sums. Grid (B=32, NCHUNK=32) = 1024 blocks, 128 thr.
// Thread owns one float4 of d. 1 FFMA per loaded float; 8 blocks/SM for MLP.
// =====================================================================
__global__ void __launch_bounds__(128, 8) k_partial(const float* __restrict__ batch,
                                                    const int* __restrict__ mask,
                                                    const int* __restrict__ types) {
    __shared__ int   t_s[CHUNK];
    __shared__ float f_s[CHUNK];
    __shared__ int   seg_s[GG + 1];
    __shared__ int   cnt_s[GG];

    const int tid = threadIdx.x;
    const int b   = blockIdx.x;
    const int c   = blockIdx.y;
    const int c0  = c * CHUNK;

    if (tid < GG + 1) seg_s[tid] = g_segstart[tid];
    if (tid < GG)     cnt_s[tid] = 0;
    __syncthreads();

    {   // stage token ids + validity flags; counts via integer smem atomics
        const int t   = g_idx[c0 + tid];
        const int gid = types[t];
        const int v   = mask[b * TT + t] ? 0 : 1;   // int32 bool: nonzero = padded
        t_s[tid] = t;
        f_s[tid] = (float)v;
        atomicAdd(&cnt_s[gid], v);
    }
    __syncthreads();

    float4 acc[GG];
#pragma unroll
    for (int g = 0; g < GG; g++) acc[g] = make_float4(0.f, 0.f, 0.f, 0.f);

    const float* bb = batch + (size_t)b * TT * DD + tid * 4;

#pragma unroll
    for (int g = 0; g < GG; g++) {
        const int jlo = max(seg_s[g],     c0) - c0;
        const int jhi = min(seg_s[g + 1], c0 + CHUNK) - c0;
#pragma unroll 4
        for (int j = jlo; j < jhi; j++) {
            const int   t = t_s[j];
            const float f = f_s[j];
            const float4 v = *(const float4*)(bb + (size_t)t * DD);
            acc[g].x = fmaf(v.x, f, acc[g].x);
            acc[g].y = fmaf(v.y, f, acc[g].y);
            acc[g].z = fmaf(v.z, f, acc[g].z);
            acc[g].w = fmaf(v.w, f, acc[g].w);
        }
    }

#pragma unroll
    for (int g = 0; g < GG; g++)
        *(float4*)&g_part[(((size_t)b * GG + g) * NCHUNK + c) * DD + tid * 4] = acc[g];
    if (tid < GG)
        g_pcnt[(b * GG + tid) * NCHUNK + c] = (float)cnt_s[tid];
}

// =====================================================================
// K2.5: reduce partials -> means [g][b][d]. Grid (B, G) = 256 blocks, 128 thr.
// =====================================================================
__global__ void __launch_bounds__(128) k_means() {
    const int b = blockIdx.x, g = blockIdx.y, tid = threadIdx.x;

    const size_t base = ((size_t)b * GG + g) * NCHUNK;
    float4 s = make_float4(0.f, 0.f, 0.f, 0.f);
    float  cnt = 0.f;
#pragma unroll 8
    for (int c = 0; c < NCHUNK; c++) {
        const float4 p = *(const float4*)&g_part[(base + c) * DD + tid * 4];
        s.x += p.x; s.y += p.y; s.z += p.z; s.w += p.w;
        cnt += g_pcnt[base + c];
    }
    const float inv = (cnt > 0.f) ? (1.0f / cnt) : 0.0f;
    s.x *= inv; s.y *= inv; s.z *= inv; s.w *= inv;
    *(float4*)&g_means[((size_t)g * BB + b) * DD + tid * 4] = s;
}

// =====================================================================
// K3: per-group GEMM + bias. Grid (G=8, OUTD/16=32) = 256 blocks, 128 thr.
// W and means staged in smem per d-quarter; compute entirely from smem.
// Thread = 1 b-row x 4 o-cols. W read exactly once chip-wide.
// =====================================================================
__global__ void __launch_bounds__(128) k_gemm(const float* __restrict__ Wt,
                                              const float* __restrict__ bias,
                                              float* __restrict__ out) {
    __shared__ float mean_s[BB * MPITCH];         // 32 x 128 (pitch 132) = 16.9 KB
    __shared__ float w_s[K3_QD * K3_OTILE];       // 128 x 16 = 8 KB

    const int tid   = threadIdx.x;
    const int g     = blockIdx.x;
    const int obase = blockIdx.y * K3_OTILE;

    const int olane = (tid & 3) * 4;              // 4 lanes x float4 = 16 cols
    const int brow  = tid >> 2;                   // 32 rows, 1 each

    const float* msrc = &g_means[(size_t)g * BB * DD];
    const float* wsrc = Wt + (size_t)g * DD * OUTD + obase;

    float4 a = make_float4(0.f, 0.f, 0.f, 0.f);

#pragma unroll
    for (int q = 0; q < DD / K3_QD; q++) {
        __syncthreads();
        // stage means[b][q*128 .. +128): 1024 float4 / 128 thr = 8 each
#pragma unroll
        for (int k = 0; k < 8; k++) {
            const int i  = tid + k * 128;
            const int bi = i >> 5;                // 32 float4 per row
            const int du = (i & 31) * 4;
            const float4 v = *(const float4*)(msrc + (size_t)bi * DD + q * K3_QD + du);
            *(float4*)&mean_s[bi * MPITCH + du] = v;
        }
        // stage W[q*128 .. +128)[obase .. +16): 512 float4 / 128 thr = 4 each
#pragma unroll
        for (int k = 0; k < 4; k++) {
            const int i   = tid + k * 128;
            const int row = i >> 2;               // 4 float4 per row
            const int col = (i & 3) * 4;
            const float4 v = *(const float4*)(wsrc + (size_t)(q * K3_QD + row) * OUTD + col);
            *(float4*)&w_s[row * K3_OTILE + col] = v;
        }
        __syncthreads();

        const float* m = &mean_s[brow * MPITCH];
#pragma unroll 8
        for (int d = 0; d < K3_QD; d++) {
            const float4 w4 = *(const float4*)&w_s[d * K3_OTILE + olane];
            const float  x  = m[d];
            a.x = fmaf(x, w4.x, a.x);
            a.y = fmaf(x, w4.y, a.y);
            a.z = fmaf(x, w4.z, a.z);
            a.w = fmaf(x, w4.w, a.w);
        }
    }

    const int o = obase + olane;
    const float4 bv = *(const float4*)(bias + g * OUTD + o);
    a.x += bv.x; a.y += bv.y; a.z += bv.z; a.w += bv.w;
    *(float4*)(out + ((size_t)brow * GG + g) * OUTD + o) = a;
}

// =====================================================================
// Launch
// =====================================================================
extern "C" void kernel_launch(void* const* d_in, const int* in_sizes, int n_in,
                              void* d_out, int out_size) {
    const float* batch = (const float*)d_in[0];
    const float* Wt    = (const float*)d_in[1];
    const float* bias  = (const float*)d_in[2];
    const int*   types = (const int*)d_in[3];
    const int*   mask  = (const int*)d_in[4];   // bool upcast to int32: nonzero = padded
    float*       out   = (float*)d_out;

    (void)in_sizes; (void)n_in; (void)out_size;

    k_sort<<<1, 512>>>(types);
    k_partial<<<dim3(BB, NCHUNK), 128>>>(batch, mask, types);
    k_means<<<dim3(BB, GG), 128>>>();
    k_gemm<<<dim3(GG, OUTD / K3_OTILE), 128>>>(Wt, bias, out);
}

// round 5
// speedup vs baseline: 5.5430x; 1.3768x over previous
#include <cuda_runtime.h>
#include <cstdint>
#include <cstddef>

// Problem constants
#define BB   32
#define TT   4096
#define DD   512
#define GG   8
#define OUTD 512

#define NCHUNK 32
#define CHUNK  128          // TT / NCHUNK == blockDim of k_partial

// K3 tiling
#define K3_OTILE 16
#define K3_QD    128        // d-quarter
#define MPITCH   132        // floats; conflict-free strided access

// -------- device scratch (no allocations allowed) --------
__device__ int   g_idx[TT];                               // token indices sorted by type
__device__ int   g_segstart[GG + 1];                      // group segment boundaries
__device__ float g_part[(size_t)BB * GG * NCHUNK * DD];   // partial sums [b][g][c][d] (16 MB)
__device__ float g_pcnt[BB * GG * NCHUNK];                // partial counts [b][g][c]
__device__ float g_means[(size_t)GG * BB * DD];           // means [g][b][d] (0.5 MB)

// =====================================================================
// K1: deterministic stable counting sort of token_types (1 block, 512 thr)
// =====================================================================
__global__ void __launch_bounds__(512) k_sort(const int* __restrict__ types) {
    __shared__ int s[GG][512];
    __shared__ int base_s[GG + 1];
    const int tid = threadIdx.x;

    int ty[8];
    int lc[GG];
#pragma unroll
    for (int g = 0; g < GG; g++) lc[g] = 0;
#pragma unroll
    for (int k = 0; k < 8; k++) {
        const int t  = tid * 8 + k;
        const int tt = types[t];
        ty[k] = tt;
#pragma unroll
        for (int g = 0; g < GG; g++) lc[g] += (tt == g);
    }
#pragma unroll
    for (int g = 0; g < GG; g++) s[g][tid] = lc[g];
    __syncthreads();

    for (int off = 1; off < 512; off <<= 1) {
        int add[GG];
#pragma unroll
        for (int g = 0; g < GG; g++) add[g] = (tid >= off) ? s[g][tid - off] : 0;
        __syncthreads();
#pragma unroll
        for (int g = 0; g < GG; g++) s[g][tid] += add[g];
        __syncthreads();
    }

    if (tid == 0) {
        int b0 = 0;
        for (int g = 0; g < GG; g++) {
            base_s[g] = b0;
            g_segstart[g] = b0;
            b0 += s[g][511];
        }
        base_s[GG] = b0;
        g_segstart[GG] = b0;
    }
    __syncthreads();

    int cur[GG];
#pragma unroll
    for (int g = 0; g < GG; g++) cur[g] = base_s[g] + s[g][tid] - lc[g];
#pragma unroll
    for (int k = 0; k < 8; k++) {
        const int t  = tid * 8 + k;
        const int tt = ty[k];
#pragma unroll
        for (int g = 0; g < GG; g++) {
            if (tt == g) { g_idx[cur[g]] = t; cur[g]++; }
        }
    }
}

// =====================================================================
// K2: segmented partial sums with VALID-TOKEN COMPACTION.
// Grid (B=32, NCHUNK=32) = 1024 blocks, 128 thr. Padded tokens (~50%)
// are never loaded. Counts derive from compacted segment bounds
// (deterministic, no atomics). Plain FADD per loaded float.
// =====================================================================
__global__ void __launch_bounds__(128, 8) k_partial(const float* __restrict__ batch,
                                                    const int* __restrict__ mask) {
    __shared__ int t_c[CHUNK];          // compacted valid token ids
    __shared__ int scan_s[CHUNK + 1];   // exclusive scan of valid flags
    __shared__ int seg_s[GG + 1];       // global segment bounds
    __shared__ int segc_s[GG + 1];      // compacted local segment bounds
    __shared__ int wsum_s[4];           // per-warp scan totals

    const int tid = threadIdx.x;
    const int b   = blockIdx.x;
    const int c   = blockIdx.y;
    const int c0  = c * CHUNK;

    if (tid < GG + 1) seg_s[tid] = g_segstart[tid];

    // ---- stage + block-wide compaction scan ----
    const int t = g_idx[c0 + tid];
    const int v = mask[b * TT + t] ? 0 : 1;   // int32 bool: nonzero = padded

    const int lane = tid & 31;
    const int w    = tid >> 5;
    int x = v;
#pragma unroll
    for (int off = 1; off < 32; off <<= 1) {
        const int y = __shfl_up_sync(0xffffffffu, x, off);
        if (lane >= off) x += y;
    }
    if (lane == 31) wsum_s[w] = x;
    __syncthreads();
    int woff = 0;
#pragma unroll
    for (int i = 0; i < 4; i++) woff += (i < w) ? wsum_s[i] : 0;
    const int incl = x + woff;
    scan_s[tid + 1] = incl;
    if (tid == 0) scan_s[0] = 0;
    if (v) { /* pos = incl - 1 */ }
    __syncthreads();
    if (v) t_c[incl - 1] = t;
    if (tid < GG + 1) {
        int lo = seg_s[tid] - c0;
        lo = lo < 0 ? 0 : (lo > CHUNK ? CHUNK : lo);
        segc_s[tid] = scan_s[lo];
    }
    __syncthreads();

    if (tid < GG)
        g_pcnt[(b * GG + tid) * NCHUNK + c] = (float)(segc_s[tid + 1] - segc_s[tid]);

    // ---- hot loop: only valid tokens, pure adds ----
    float4 acc[GG];
#pragma unroll
    for (int g = 0; g < GG; g++) acc[g] = make_float4(0.f, 0.f, 0.f, 0.f);

    const float* bb = batch + (size_t)b * TT * DD + tid * 4;

#pragma unroll
    for (int g = 0; g < GG; g++) {
        const int jlo = segc_s[g];
        const int jhi = segc_s[g + 1];
#pragma unroll 4
        for (int j = jlo; j < jhi; j++) {
            const int tt2 = t_c[j];
            const float4 v4 = *(const float4*)(bb + (size_t)tt2 * DD);
            acc[g].x += v4.x; acc[g].y += v4.y; acc[g].z += v4.z; acc[g].w += v4.w;
        }
    }

#pragma unroll
    for (int g = 0; g < GG; g++)
        *(float4*)&g_part[(((size_t)b * GG + g) * NCHUNK + c) * DD + tid * 4] = acc[g];
}

// =====================================================================
// K2.5: reduce partials -> means [g][b][d]. Grid (B, G) = 256 blocks, 128 thr.
// =====================================================================
__global__ void __launch_bounds__(128) k_means() {
    const int b = blockIdx.x, g = blockIdx.y, tid = threadIdx.x;

    const size_t base = ((size_t)b * GG + g) * NCHUNK;
    float4 s = make_float4(0.f, 0.f, 0.f, 0.f);
    float  cnt = 0.f;
#pragma unroll 8
    for (int c = 0; c < NCHUNK; c++) {
        const float4 p = *(const float4*)&g_part[(base + c) * DD + tid * 4];
        s.x += p.x; s.y += p.y; s.z += p.z; s.w += p.w;
        cnt += g_pcnt[base + c];
    }
    const float inv = (cnt > 0.f) ? (1.0f / cnt) : 0.0f;
    s.x *= inv; s.y *= inv; s.z *= inv; s.w *= inv;
    *(float4*)&g_means[((size_t)g * BB + b) * DD + tid * 4] = s;
}

// =====================================================================
// K3: per-group GEMM + bias with register double-buffering.
// Grid (G=8, OUTD/16=32) = 256 blocks, 128 thr. Quarter q+1's W and
// means tiles are prefetched into registers while q computes from smem.
// =====================================================================
__global__ void __launch_bounds__(128) k_gemm(const float* __restrict__ Wt,
                                              const float* __restrict__ bias,
                                              float* __restrict__ out) {
    __shared__ float mean_s[BB * MPITCH];         // 32 x 128 (pitch 132)
    __shared__ float w_s[K3_QD * K3_OTILE];       // 128 x 16

    const int tid   = threadIdx.x;
    const int g     = blockIdx.x;
    const int obase = blockIdx.y * K3_OTILE;

    const int olane = (tid & 3) * 4;              // 4 lanes x float4 = 16 cols
    const int brow  = tid >> 2;                   // 32 rows, 1 each

    const float* msrc = &g_means[(size_t)g * BB * DD];
    const float* wsrc = Wt + (size_t)g * DD * OUTD + obase;

    // prefetch register buffers
    float4 mpre[8];
    float4 wpre[4];

    // thread's fixed staging coordinates
    int m_bi[8], m_du[8], w_row[4], w_col[4];
#pragma unroll
    for (int k = 0; k < 8; k++) {
        const int i = tid + k * 128;
        m_bi[k] = i >> 5;
        m_du[k] = (i & 31) * 4;
    }
#pragma unroll
    for (int k = 0; k < 4; k++) {
        const int i = tid + k * 128;
        w_row[k] = i >> 2;
        w_col[k] = (i & 3) * 4;
    }

    // issue loads for q = 0
#pragma unroll
    for (int k = 0; k < 8; k++)
        mpre[k] = *(const float4*)(msrc + (size_t)m_bi[k] * DD + m_du[k]);
#pragma unroll
    for (int k = 0; k < 4; k++)
        wpre[k] = *(const float4*)(wsrc + (size_t)w_row[k] * OUTD + w_col[k]);

    float4 a = make_float4(0.f, 0.f, 0.f, 0.f);

#pragma unroll
    for (int q = 0; q < DD / K3_QD; q++) {
        __syncthreads();
#pragma unroll
        for (int k = 0; k < 8; k++)
            *(float4*)&mean_s[m_bi[k] * MPITCH + m_du[k]] = mpre[k];
#pragma unroll
        for (int k = 0; k < 4; k++)
            *(float4*)&w_s[w_row[k] * K3_OTILE + w_col[k]] = wpre[k];

        if (q < DD / K3_QD - 1) {
            const int qn = (q + 1) * K3_QD;
#pragma unroll
            for (int k = 0; k < 8; k++)
                mpre[k] = *(const float4*)(msrc + (size_t)m_bi[k] * DD + qn + m_du[k]);
#pragma unroll
            for (int k = 0; k < 4; k++)
                wpre[k] = *(const float4*)(wsrc + (size_t)(qn + w_row[k]) * OUTD + w_col[k]);
        }
        __syncthreads();

        const float* m = &mean_s[brow * MPITCH];
#pragma unroll 8
        for (int d = 0; d < K3_QD; d++) {
            const float4 w4 = *(const float4*)&w_s[d * K3_OTILE + olane];
            const float  x  = m[d];
            a.x = fmaf(x, w4.x, a.x);
            a.y = fmaf(x, w4.y, a.y);
            a.z = fmaf(x, w4.z, a.z);
            a.w = fmaf(x, w4.w, a.w);
        }
    }

    const int o = obase + olane;
    const float4 bv = *(const float4*)(bias + g * OUTD + o);
    a.x += bv.x; a.y += bv.y; a.z += bv.z; a.w += bv.w;
    *(float4*)(out + ((size_t)brow * GG + g) * OUTD + o) = a;
}

// =====================================================================
// Launch
// =====================================================================
extern "C" void kernel_launch(void* const* d_in, const int* in_sizes, int n_in,
                              void* d_out, int out_size) {
    const float* batch = (const float*)d_in[0];
    const float* Wt    = (const float*)d_in[1];
    const float* bias  = (const float*)d_in[2];
    const int*   types = (const int*)d_in[3];
    const int*   mask  = (const int*)d_in[4];   // bool upcast to int32: nonzero = padded
    float*       out   = (float*)d_out;

    (void)in_sizes; (void)n_in; (void)out_size;

    k_sort<<<1, 512>>>(types);
    k_partial<<<dim3(BB, NCHUNK), 128>>>(batch, mask);
    k_means<<<dim3(BB, GG), 128>>>();
    k_gemm<<<dim3(GG, OUTD / K3_OTILE), 128>>>(Wt, bias, out);
}

// round 6
// speedup vs baseline: 5.9229x; 1.0685x over previous
#include <cuda_runtime.h>
#include <cstdint>
#include <cstddef>

// Problem constants
#define BB   32
#define TT   4096
#define DD   512
#define GG   8
#define OUTD 512

#define NCHUNK 32
#define CHUNK  128          // TT / NCHUNK == blockDim of k_partial

// K3 tiling: one-shot tiles, split-K over 8 d-tiles of 64
#define K3B   32            // o-tile width
#define K3D   64            // d-tile depth
#define K3_ND (DD / K3D)    // 8
#define MP3   68            // mean smem pitch (floats): 16B-aligned, conflict-free

// -------- device scratch (no allocations allowed) --------
__device__ int   g_idx[TT];                               // token indices sorted by type
__device__ int   g_segstart[GG + 1];                      // group segment boundaries
__device__ float g_part[(size_t)BB * GG * NCHUNK * DD];   // partial sums [b][g][c][d] (16 MB)
__device__ float g_pcnt[BB * GG * NCHUNK];                // partial counts [b][g][c]
__device__ float g_means[(size_t)GG * BB * DD];           // means [g][b][d] (0.5 MB)
__device__ float g_ppart[(size_t)K3_ND * BB * GG * OUTD]; // gemm partials [dq][b][g][o] (4 MB)

// =====================================================================
// K1: deterministic stable counting sort of token_types (1 block, 512 thr)
// =====================================================================
__global__ void __launch_bounds__(512) k_sort(const int* __restrict__ types) {
    __shared__ int s[GG][512];
    __shared__ int base_s[GG + 1];
    const int tid = threadIdx.x;

    int ty[8];
    int lc[GG];
#pragma unroll
    for (int g = 0; g < GG; g++) lc[g] = 0;
#pragma unroll
    for (int k = 0; k < 8; k++) {
        const int t  = tid * 8 + k;
        const int tt = types[t];
        ty[k] = tt;
#pragma unroll
        for (int g = 0; g < GG; g++) lc[g] += (tt == g);
    }
#pragma unroll
    for (int g = 0; g < GG; g++) s[g][tid] = lc[g];
    __syncthreads();

    for (int off = 1; off < 512; off <<= 1) {
        int add[GG];
#pragma unroll
        for (int g = 0; g < GG; g++) add[g] = (tid >= off) ? s[g][tid - off] : 0;
        __syncthreads();
#pragma unroll
        for (int g = 0; g < GG; g++) s[g][tid] += add[g];
        __syncthreads();
    }

    if (tid == 0) {
        int b0 = 0;
        for (int g = 0; g < GG; g++) {
            base_s[g] = b0;
            g_segstart[g] = b0;
            b0 += s[g][511];
        }
        base_s[GG] = b0;
        g_segstart[GG] = b0;
    }
    __syncthreads();

    int cur[GG];
#pragma unroll
    for (int g = 0; g < GG; g++) cur[g] = base_s[g] + s[g][tid] - lc[g];
#pragma unroll
    for (int k = 0; k < 8; k++) {
        const int t  = tid * 8 + k;
        const int tt = ty[k];
#pragma unroll
        for (int g = 0; g < GG; g++) {
            if (tt == g) { g_idx[cur[g]] = t; cur[g]++; }
        }
    }
}

// =====================================================================
// K2: segmented partial sums with valid-token compaction.
// Grid (B=32, NCHUNK=32) = 1024 blocks, 128 thr. Streaming loads.
// =====================================================================
__global__ void __launch_bounds__(128, 8) k_partial(const float* __restrict__ batch,
                                                    const int* __restrict__ mask) {
    __shared__ int t_c[CHUNK];          // compacted valid token ids
    __shared__ int scan_s[CHUNK + 1];   // exclusive scan of valid flags
    __shared__ int seg_s[GG + 1];       // global segment bounds
    __shared__ int segc_s[GG + 1];      // compacted local segment bounds
    __shared__ int wsum_s[4];           // per-warp scan totals

    const int tid = threadIdx.x;
    const int b   = blockIdx.x;
    const int c   = blockIdx.y;
    const int c0  = c * CHUNK;

    if (tid < GG + 1) seg_s[tid] = g_segstart[tid];

    // ---- stage + block-wide compaction scan ----
    const int t = g_idx[c0 + tid];
    const int v = mask[b * TT + t] ? 0 : 1;   // int32 bool: nonzero = padded

    const int lane = tid & 31;
    const int w    = tid >> 5;
    int x = v;
#pragma unroll
    for (int off = 1; off < 32; off <<= 1) {
        const int y = __shfl_up_sync(0xffffffffu, x, off);
        if (lane >= off) x += y;
    }
    if (lane == 31) wsum_s[w] = x;
    __syncthreads();
    int woff = 0;
#pragma unroll
    for (int i = 0; i < 4; i++) woff += (i < w) ? wsum_s[i] : 0;
    const int incl = x + woff;
    scan_s[tid + 1] = incl;
    if (tid == 0) scan_s[0] = 0;
    __syncthreads();
    if (v) t_c[incl - 1] = t;
    if (tid < GG + 1) {
        int lo = seg_s[tid] - c0;
        lo = lo < 0 ? 0 : (lo > CHUNK ? CHUNK : lo);
        segc_s[tid] = scan_s[lo];
    }
    __syncthreads();

    if (tid < GG)
        g_pcnt[(b * GG + tid) * NCHUNK + c] = (float)(segc_s[tid + 1] - segc_s[tid]);

    // ---- hot loop: only valid tokens, streaming float4 loads, pure adds ----
    float4 acc[GG];
#pragma unroll
    for (int g = 0; g < GG; g++) acc[g] = make_float4(0.f, 0.f, 0.f, 0.f);

    const float* bb = batch + (size_t)b * TT * DD + tid * 4;

#pragma unroll
    for (int g = 0; g < GG; g++) {
        const int jlo = segc_s[g];
        const int jhi = segc_s[g + 1];
#pragma unroll 8
        for (int j = jlo; j < jhi; j++) {
            const int tt2 = t_c[j];
            const float4 v4 = __ldcs((const float4*)(bb + (size_t)tt2 * DD));
            acc[g].x += v4.x; acc[g].y += v4.y; acc[g].z += v4.z; acc[g].w += v4.w;
        }
    }

#pragma unroll
    for (int g = 0; g < GG; g++)
        *(float4*)&g_part[(((size_t)b * GG + g) * NCHUNK + c) * DD + tid * 4] = acc[g];
}

// =====================================================================
// K2.5: reduce partials -> means [g][b][d]. Grid (B, G) = 256 blocks, 128 thr.
// Partials are L2-resident (16 MB); single-use streaming loads.
// =====================================================================
__global__ void __launch_bounds__(128) k_means() {
    const int b = blockIdx.x, g = blockIdx.y, tid = threadIdx.x;

    const size_t base = ((size_t)b * GG + g) * NCHUNK;
    float4 s = make_float4(0.f, 0.f, 0.f, 0.f);
    float  cnt = 0.f;
#pragma unroll 8
    for (int c = 0; c < NCHUNK; c++) {
        const float4 p = __ldcs((const float4*)&g_part[(base + c) * DD + tid * 4]);
        s.x += p.x; s.y += p.y; s.z += p.z; s.w += p.w;
        cnt += g_pcnt[base + c];
    }
    const float inv = (cnt > 0.f) ? (1.0f / cnt) : 0.0f;
    s.x *= inv; s.y *= inv; s.z *= inv; s.w *= inv;
    *(float4*)&g_means[((size_t)g * BB + b) * DD + tid * 4] = s;
}

// =====================================================================
// K3: split-K GEMM. Grid (G=8, 16 o-tiles, 8 d-tiles) = 1024 blocks, 128 thr.
// Each block: load one 64x32 W tile + 32x64 mean tile (once, full MLP),
// compute 2b x 4o per thread over k=64, write partial [dq][b][g][o].
// =====================================================================
__global__ void __launch_bounds__(128) k_gemm3(const float* __restrict__ Wt) {
    __shared__ float w_s[K3D * K3B];     // 64 x 32 = 8 KB, pitch 32
    __shared__ float mean_s[BB * MP3];   // 32 x 64 (pitch 68) = 8.7 KB

    const int tid   = threadIdx.x;
    const int g     = blockIdx.x;
    const int obase = blockIdx.y * K3B;
    const int dbase = blockIdx.z * K3D;

    const float* msrc = &g_means[(size_t)g * BB * DD + dbase];
    const float* wsrc = Wt + ((size_t)g * DD + dbase) * OUTD + obase;

    // stage W tile: 512 float4, 4 per thread (coalesced)
#pragma unroll
    for (int k = 0; k < 4; k++) {
        const int i   = tid + k * 128;
        const int row = i >> 3;            // 8 float4 per 32-col row
        const int col = (i & 7) * 4;
        const float4 v = *(const float4*)(wsrc + (size_t)row * OUTD + col);
        *(float4*)&w_s[row * K3B + col] = v;
    }
    // stage mean tile: 512 float4, 4 per thread (coalesced)
#pragma unroll
    for (int k = 0; k < 4; k++) {
        const int i  = tid + k * 128;
        const int bi = i >> 4;             // 16 float4 per 64-col row
        const int du = (i & 15) * 4;
        const float4 v = *(const float4*)(msrc + (size_t)bi * DD + du);
        *(float4*)&mean_s[bi * MP3 + du] = v;
    }
    __syncthreads();

    const int olane = (tid & 7) * 4;       // 8 lanes x float4 = 32 cols
    const int brow  = (tid >> 3) * 2;      // 16 x 2 = 32 rows

    const float* m0 = &mean_s[brow * MP3];
    const float* m1 = m0 + MP3;

    float4 a0 = make_float4(0.f, 0.f, 0.f, 0.f);
    float4 a1 = make_float4(0.f, 0.f, 0.f, 0.f);

#pragma unroll 8
    for (int d = 0; d < K3D; d++) {
        const float4 w4 = *(const float4*)&w_s[d * K3B + olane];
        const float  x0 = m0[d];
        const float  x1 = m1[d];
        a0.x = fmaf(x0, w4.x, a0.x); a0.y = fmaf(x0, w4.y, a0.y);
        a0.z = fmaf(x0, w4.z, a0.z); a0.w = fmaf(x0, w4.w, a0.w);
        a1.x = fmaf(x1, w4.x, a1.x); a1.y = fmaf(x1, w4.y, a1.y);
        a1.z = fmaf(x1, w4.z, a1.z); a1.w = fmaf(x1, w4.w, a1.w);
    }

    const int dq = blockIdx.z;
    const int o  = obase + olane;
    *(float4*)&g_ppart[(((size_t)dq * BB + brow)     * GG + g) * OUTD + o] = a0;
    *(float4*)&g_ppart[(((size_t)dq * BB + brow + 1) * GG + g) * OUTD + o] = a1;
}

// =====================================================================
// K4: reduce split-K partials + bias -> out. Grid (B, G) = 256 blocks.
// Partials are L2-resident (4 MB). Deterministic ascending dq order.
// =====================================================================
__global__ void __launch_bounds__(128) k_out(const float* __restrict__ bias,
                                             float* __restrict__ out) {
    const int b = blockIdx.x, g = blockIdx.y, tid = threadIdx.x;
    const int o = tid * 4;

    float4 s = *(const float4*)(bias + g * OUTD + o);
#pragma unroll
    for (int dq = 0; dq < K3_ND; dq++) {
        const float4 p = __ldcs((const float4*)&g_ppart[(((size_t)dq * BB + b) * GG + g) * OUTD + o]);
        s.x += p.x; s.y += p.y; s.z += p.z; s.w += p.w;
    }
    *(float4*)(out + ((size_t)b * GG + g) * OUTD + o) = s;
}

// =====================================================================
// Launch
// =====================================================================
extern "C" void kernel_launch(void* const* d_in, const int* in_sizes, int n_in,
                              void* d_out, int out_size) {
    const float* batch = (const float*)d_in[0];
    const float* Wt    = (const float*)d_in[1];
    const float* bias  = (const float*)d_in[2];
    const int*   types = (const int*)d_in[3];
    const int*   mask  = (const int*)d_in[4];   // bool upcast to int32: nonzero = padded
    float*       out   = (float*)d_out;

    (void)in_sizes; (void)n_in; (void)out_size;

    k_sort<<<1, 512>>>(types);
    k_partial<<<dim3(BB, NCHUNK), 128>>>(batch, mask);
    k_means<<<dim3(BB, GG), 128>>>();
    k_gemm3<<<dim3(GG, OUTD / K3B, K3_ND), 128>>>(Wt);
    k_out<<<dim3(BB, GG), 128>>>(bias, out);
}